// round 5
// baseline (speedup 1.0000x reference)
#include <cuda_runtime.h>
#include <cstdint>

// Problem constants (B=16, H=W=1024)
#define HW_SHIFT 20            // H*W = 1<<20
#define W_SHIFT  10            // W = 1024
#define W_DIM    1024
#define HW_DIM   (1 << HW_SHIFT)
#define TOTAL_PIX (16 * HW_DIM)        // 16,777,216
#define PIX_PER_THREAD 8
#define THREADS 256
#define BLOCKS (TOTAL_PIX / (PIX_PER_THREAD * THREADS))   // 8192
#define EPSF 1e-7f

__device__ float        g_scratch = 0.0f;
__device__ unsigned int g_count   = 0;

__global__ __launch_bounds__(THREADS, 1)
void confidence_loss_kernel(const float* __restrict__ o_f,
                            const int* __restrict__ target,
                            float* __restrict__ out) {
    const long long tid  = (long long)blockIdx.x * THREADS + threadIdx.x;
    const long long base = tid * PIX_PER_THREAD;          // first pixel index

    const int b   = (int)(base >> HW_SHIFT);
    const int rem = (int)(base & (HW_DIM - 1));
    const int i   = rem >> W_SHIFT;
    const int j   = rem & (W_DIM - 1);

    // Front-batched vector loads (MLP=8). Channel planes are [B,3,H,W].
    const float* p0 = o_f + (size_t)b * 3 * HW_DIM + rem;
    const float4 f0a = *(const float4*)(p0);
    const float4 f0b = *(const float4*)(p0 + 4);
    const float4 f1a = *(const float4*)(p0 + HW_DIM);
    const float4 f1b = *(const float4*)(p0 + HW_DIM + 4);
    const float4 f2a = *(const float4*)(p0 + 2 * HW_DIM);
    const float4 f2b = *(const float4*)(p0 + 2 * HW_DIM + 4);

    const int* tbase = target + (size_t)b * HW_DIM;
    const int4 t4a = *(const int4*)(tbase + rem);
    const int4 t4b = *(const int4*)(tbase + rem + 4);

    float o0v[8] = {f0a.x, f0a.y, f0a.z, f0a.w, f0b.x, f0b.y, f0b.z, f0b.w};
    float o1v[8] = {f1a.x, f1a.y, f1a.z, f1a.w, f1b.x, f1b.y, f1b.z, f1b.w};
    float fv [8] = {f2a.x, f2a.y, f2a.z, f2a.w, f2b.x, f2b.y, f2b.z, f2b.w};
    int   tv [8] = {t4a.x, t4a.y, t4a.z, t4a.w, t4b.x, t4b.y, t4b.z, t4b.w};

    float acc = 0.0f;

#pragma unroll
    for (int k = 0; k < PIX_PER_THREAD; k++) {
        const int jj = j + k;

        int x = (int)floorf(o0v[k] + (float)jj);
        int y = (int)floorf(o1v[k] + (float)i);
        x = min(max(x, 0), W_DIM - 1);
        y = min(max(y, 0), W_DIM - 1);

        // remap IGNORE_LABEL (-1) -> 0
        const int town = tv[k];
        const int tt = (town == -1) ? 0 : town;

        int hs;
        if (x == jj && y == i) {
            // common case for this data (offsets in [0,1)): gather is identity
            hs = tt;
        } else {
            const int g = __ldg(tbase + (y << W_SHIFT) + x);
            hs = (g == -1) ? 0 : g;
        }

        const float f = fv[k];
        const float arg = ((tt == hs) ? f : (1.0f - f)) + EPSF;
        acc -= __logf(arg);
    }

    // Warp reduction
#pragma unroll
    for (int off = 16; off > 0; off >>= 1)
        acc += __shfl_xor_sync(0xFFFFFFFFu, acc, off);

    // Block reduction via shared memory
    __shared__ float warp_sums[THREADS / 32];
    const int lane = threadIdx.x & 31;
    const int wid  = threadIdx.x >> 5;
    if (lane == 0) warp_sums[wid] = acc;
    __syncthreads();

    if (wid == 0 && lane < THREADS / 32) {
        float s = warp_sums[lane];
#pragma unroll
        for (int off = 4; off > 0; off >>= 1)
            s += __shfl_xor_sync(0xFFu, s, off);

        if (lane == 0) {
            atomicAdd(&g_scratch, s);
            __threadfence();
            const unsigned int done = atomicAdd(&g_count, 1u);
            if (done == (unsigned int)(BLOCKS - 1)) {
                // last block: all other adds are visible (fence + counter order)
                const float total = *((volatile float*)&g_scratch);
                out[0] = total * (1.0f / (float)TOTAL_PIX);   // W_F * mean
                // reset for the next graph replay (deterministic)
                g_scratch = 0.0f;
                g_count   = 0;
            }
        }
    }
}

extern "C" void kernel_launch(void* const* d_in, const int* in_sizes, int n_in,
                              void* d_out, int out_size) {
    const float* o_f    = (const float*)d_in[0];
    const int*   target = (const int*)d_in[1];
    float*       out    = (float*)d_out;

    confidence_loss_kernel<<<BLOCKS, THREADS>>>(o_f, target, out);
}

// round 6
// speedup vs baseline: 1.0433x; 1.0433x over previous
#include <cuda_runtime.h>
#include <cstdint>

// Problem constants (B=16, H=W=1024)
#define HW_SHIFT 20            // H*W = 1<<20
#define W_SHIFT  10            // W = 1024
#define W_DIM    1024
#define HW_DIM   (1 << HW_SHIFT)
#define TOTAL_PIX (16 * HW_DIM)        // 16,777,216
#define PIX_PER_THREAD 4
#define THREADS 256
#define BLOCKS (TOTAL_PIX / (PIX_PER_THREAD * THREADS))   // 16384
#define EPSF 1e-7f

__device__ float        g_scratch = 0.0f;
__device__ unsigned int g_count   = 0;

__global__ __launch_bounds__(THREADS, 1)
void confidence_loss_kernel(const float* __restrict__ o_f,
                            const int* __restrict__ target,
                            float* __restrict__ out) {
    const long long tid  = (long long)blockIdx.x * THREADS + threadIdx.x;
    const long long base = tid * PIX_PER_THREAD;          // first pixel index

    const int b   = (int)(base >> HW_SHIFT);
    const int rem = (int)(base & (HW_DIM - 1));
    const int i   = rem >> W_SHIFT;
    const int j   = rem & (W_DIM - 1);

    // Vectorized loads (MLP=4): channel planes are [B,3,H,W] contiguous.
    const float* p0 = o_f + (size_t)b * 3 * HW_DIM + rem;     // channel 0
    const float4 f0 = *(const float4*)(p0);
    const float4 f1 = *(const float4*)(p0 + HW_DIM);          // channel 1
    const float4 f2 = *(const float4*)(p0 + 2 * HW_DIM);      // channel 2

    const int* tbase = target + (size_t)b * HW_DIM;
    const int4 t4 = *(const int4*)(tbase + rem);

    float o0v[4] = {f0.x, f0.y, f0.z, f0.w};
    float o1v[4] = {f1.x, f1.y, f1.z, f1.w};
    float fv [4] = {f2.x, f2.y, f2.z, f2.w};
    int   tv [4] = {t4.x, t4.y, t4.z, t4.w};

    float acc = 0.0f;

#pragma unroll
    for (int k = 0; k < PIX_PER_THREAD; k++) {
        const int jj = j + k;

        int x = (int)floorf(o0v[k] + (float)jj);
        int y = (int)floorf(o1v[k] + (float)i);
        x = min(max(x, 0), W_DIM - 1);
        y = min(max(y, 0), W_DIM - 1);

        // remap IGNORE_LABEL (-1) -> 0
        const int town = tv[k];
        const int tt = (town == -1) ? 0 : town;

        int hs;
        if (x == jj && y == i) {
            // common case for this data (offsets in [0,1)): gather is identity
            hs = tt;
        } else {
            const int g = __ldg(tbase + (y << W_SHIFT) + x);
            hs = (g == -1) ? 0 : g;
        }

        const float f = fv[k];
        const float arg = ((tt == hs) ? f : (1.0f - f)) + EPSF;
        acc -= __logf(arg);
    }

    // Warp reduction
#pragma unroll
    for (int off = 16; off > 0; off >>= 1)
        acc += __shfl_xor_sync(0xFFFFFFFFu, acc, off);

    // Block reduction via shared memory
    __shared__ float warp_sums[THREADS / 32];
    const int lane = threadIdx.x & 31;
    const int wid  = threadIdx.x >> 5;
    if (lane == 0) warp_sums[wid] = acc;
    __syncthreads();

    if (wid == 0 && lane < THREADS / 32) {
        float s = warp_sums[lane];
#pragma unroll
        for (int off = 4; off > 0; off >>= 1)
            s += __shfl_xor_sync(0xFFu, s, off);

        if (lane == 0) {
            atomicAdd(&g_scratch, s);
            __threadfence();
            const unsigned int done = atomicAdd(&g_count, 1u);
            if (done == (unsigned int)(BLOCKS - 1)) {
                // last block: all other adds visible (fence + counter order)
                const float total = *((volatile float*)&g_scratch);
                out[0] = total * (1.0f / (float)TOTAL_PIX);   // W_F * mean
                // reset for the next graph replay (deterministic)
                g_scratch = 0.0f;
                g_count   = 0;
            }
        }
    }
}

extern "C" void kernel_launch(void* const* d_in, const int* in_sizes, int n_in,
                              void* d_out, int out_size) {
    const float* o_f    = (const float*)d_in[0];
    const int*   target = (const int*)d_in[1];
    float*       out    = (float*)d_out;

    confidence_loss_kernel<<<BLOCKS, THREADS>>>(o_f, target, out);
}